// round 2
// baseline (speedup 1.0000x reference)
#include <cuda_runtime.h>

#define NN 8000
#define NE 128000
#define FF 128
#define ZZ 10
#define RR 8
#define HH 64

#define SQ3f      1.7320508075688772f
#define INV_SQ3   0.5773502691896258f
#define INV_SQF   0.08838834764831845f    // 1/sqrt(128)
#define INV_SQR   0.35355339059327373f    // 1/sqrt(8)
#define INV_SQZ   0.31622776601683794f
#define INV_SQFZ  0.027950849718747374f   // 1/(sqrt(128)*sqrt(10))
#define EPSf      0.25f

// ---------------- scratch (device globals; no allocation allowed) -------------
__device__ float g_x0[NN * FF];        // linear_up scalar   [N,F]
__device__ float g_x1[NN * FF * 3];    // linear_up vector   [N,F,3]
__device__ float g_a0[NN * FF];        // scattered messages [N,F]
__device__ float g_a1[NN * FF * 3];    // scattered messages [N,F,3]
__device__ int   g_cnt[ZZ];
__device__ int   g_fill[ZZ];
__device__ int   g_off[ZZ];
__device__ int   g_bucket[NN];         // node ids grouped by species

__device__ __forceinline__ float silu(float x) {
    return x / (1.f + __expf(-x));
}

// ---------------- zero scratch ------------------------------------------------
__global__ void zero_kernel() {
    int i = blockIdx.x * blockDim.x + threadIdx.x;
    int stride = gridDim.x * blockDim.x;
    for (int k = i; k < NN * FF; k += stride)      g_a0[k] = 0.f;
    for (int k = i; k < NN * FF * 3; k += stride)  g_a1[k] = 0.f;
    if (i < ZZ) { g_cnt[i] = 0; g_fill[i] = 0; }
}

// ---------------- species bucketing -------------------------------------------
__global__ void count_kernel(const int* __restrict__ species) {
    int i = blockIdx.x * blockDim.x + threadIdx.x;
    if (i < NN) atomicAdd(&g_cnt[species[i]], 1);
}

__global__ void scan_kernel() {
    if (threadIdx.x == 0) {
        int acc = 0;
        for (int z = 0; z < ZZ; z++) { g_off[z] = acc; acc += g_cnt[z]; }
    }
}

__global__ void fill_kernel(const int* __restrict__ species) {
    int i = blockIdx.x * blockDim.x + threadIdx.x;
    if (i < NN) {
        int sp = species[i];
        int pos = g_off[sp] + atomicAdd(&g_fill[sp], 1);
        g_bucket[pos] = i;
    }
}

// ---------------- linear_up: x0 = nf0@Wu0/sqF, x1 = nf1@Wu1/sqF ---------------
// 8 nodes per block, 128 threads (thread = output channel g)
__global__ void __launch_bounds__(128) up_kernel(
    const float* __restrict__ nf0, const float* __restrict__ nf1,
    const float* __restrict__ w0, const float* __restrict__ w1)
{
    __shared__ float s0[8 * 128];
    __shared__ float s1[8 * 384];
    const int n0 = blockIdx.x * 8;
    const int t = threadIdx.x;

    for (int idx = t; idx < 8 * 128; idx += 128) s0[idx] = nf0[n0 * 128 + idx];
    for (int idx = t; idx < 8 * 384; idx += 128) s1[idx] = nf1[n0 * 384 + idx];
    __syncthreads();

    float a0[8], ax[8], ay[8], az[8];
#pragma unroll
    for (int j = 0; j < 8; j++) { a0[j] = ax[j] = ay[j] = az[j] = 0.f; }

#pragma unroll 4
    for (int f = 0; f < 128; f++) {
        float w0v = w0[f * 128 + t];
        float w1v = w1[f * 128 + t];
#pragma unroll
        for (int j = 0; j < 8; j++) {
            a0[j] = fmaf(s0[j * 128 + f],        w0v, a0[j]);
            ax[j] = fmaf(s1[j * 384 + f * 3 + 0], w1v, ax[j]);
            ay[j] = fmaf(s1[j * 384 + f * 3 + 1], w1v, ay[j]);
            az[j] = fmaf(s1[j * 384 + f * 3 + 2], w1v, az[j]);
        }
    }
#pragma unroll
    for (int j = 0; j < 8; j++) {
        int n = n0 + j;
        g_x0[n * 128 + t]           = a0[j] * INV_SQF;
        g_x1[(n * 128 + t) * 3 + 0] = ax[j] * INV_SQF;
        g_x1[(n * 128 + t) * 3 + 1] = ay[j] * INV_SQF;
        g_x1[(n * 128 + t) * 3 + 2] = az[j] * INV_SQF;
    }
}

// ---------------- edge kernel: radial MLP + TP messages + scatter -------------
// 32 edges per block, 256 threads.
// Layers 1-3: thread = (edge-group, hidden j). Layer 4 fused with message math:
// thread = (edge-group of 16, channel f); the 5 mix paths stay in registers.
__global__ void __launch_bounds__(256) edge_kernel(
    const float* __restrict__ vectors, const float* __restrict__ radial,
    const int* __restrict__ senders, const int* __restrict__ receivers,
    const float* __restrict__ mw1, const float* __restrict__ mw2,
    const float* __restrict__ mw3, const float* __restrict__ mw4)
{
    __shared__ float ha[32 * 64];
    __shared__ float hb[32 * 64];
    __shared__ float rad[32 * 8];
    __shared__ float y1s[32 * 3];
    __shared__ int   snd[32];
    __shared__ int   rcv[32];

    const int t = threadIdx.x;
    const int e_base = blockIdx.x * 32;

    rad[t] = radial[e_base * 8 + t];           // 256 = 32*8 exactly
    if (t < 32) {
        int e = e_base + t;
        snd[t] = senders[e];
        rcv[t] = receivers[e];
        float vx = vectors[e * 3 + 0], vy = vectors[e * 3 + 1], vz = vectors[e * 3 + 2];
        float rn = sqrtf(vx * vx + vy * vy + vz * vz) + 1e-12f;
        float sc = SQ3f / rn;
        y1s[t * 3 + 0] = vx * sc;
        y1s[t * 3 + 1] = vy * sc;
        y1s[t * 3 + 2] = vz * sc;
    }
    __syncthreads();

    const int j = t & 63;
    const int grp = t >> 6;   // 0..3, 8 edges each

    // ---- layer 1: [8 -> 64], silu((r@w1)/sqrt(8))
#pragma unroll
    for (int e8 = 0; e8 < 8; e8++) {
        int e = grp * 8 + e8;
        float acc = 0.f;
#pragma unroll
        for (int k = 0; k < 8; k++) acc = fmaf(rad[e * 8 + k], mw1[k * 64 + j], acc);
        ha[e * 64 + j] = silu(acc * INV_SQR);
    }
    __syncthreads();

    // ---- layer 2: [64 -> 64], silu(/8)
    {
        float acc[8];
#pragma unroll
        for (int e8 = 0; e8 < 8; e8++) acc[e8] = 0.f;
#pragma unroll 4
        for (int k = 0; k < 64; k++) {
            float w = mw2[k * 64 + j];
#pragma unroll
            for (int e8 = 0; e8 < 8; e8++)
                acc[e8] = fmaf(ha[(grp * 8 + e8) * 64 + k], w, acc[e8]);
        }
#pragma unroll
        for (int e8 = 0; e8 < 8; e8++)
            hb[(grp * 8 + e8) * 64 + j] = silu(acc[e8] * 0.125f);
    }
    __syncthreads();

    // ---- layer 3: [64 -> 64], silu(/8) -> back into ha
    {
        float acc[8];
#pragma unroll
        for (int e8 = 0; e8 < 8; e8++) acc[e8] = 0.f;
#pragma unroll 4
        for (int k = 0; k < 64; k++) {
            float w = mw3[k * 64 + j];
#pragma unroll
            for (int e8 = 0; e8 < 8; e8++)
                acc[e8] = fmaf(hb[(grp * 8 + e8) * 64 + k], w, acc[e8]);
        }
        __syncthreads();   // everyone done reading hb? (hb not reused; sync for ha write hazard)
#pragma unroll
        for (int e8 = 0; e8 < 8; e8++)
            hb[(grp * 8 + e8) * 64 + j] = silu(acc[e8] * 0.125f);  // h3 lives in hb
    }
    __syncthreads();

    // ---- layer 4 [64 -> 5*128] fused with tensor-product messages
    const int f = t & 127;
    const int eg = t >> 7;       // 0/1
    const int e0 = eg * 16;

    float acc[80];
#pragma unroll
    for (int i = 0; i < 80; i++) acc[i] = 0.f;

#pragma unroll 2
    for (int k = 0; k < 64; k++) {
        const float* w4row = mw4 + k * 640;
        float wv0 = w4row[0 * 128 + f];
        float wv1 = w4row[1 * 128 + f];
        float wv2 = w4row[2 * 128 + f];
        float wv3 = w4row[3 * 128 + f];
        float wv4 = w4row[4 * 128 + f];
#pragma unroll
        for (int ee = 0; ee < 16; ee++) {
            float h = hb[(e0 + ee) * 64 + k];
            acc[0 * 16 + ee] = fmaf(wv0, h, acc[0 * 16 + ee]);
            acc[1 * 16 + ee] = fmaf(wv1, h, acc[1 * 16 + ee]);
            acc[2 * 16 + ee] = fmaf(wv2, h, acc[2 * 16 + ee]);
            acc[3 * 16 + ee] = fmaf(wv3, h, acc[3 * 16 + ee]);
            acc[4 * 16 + ee] = fmaf(wv4, h, acc[4 * 16 + ee]);
        }
    }

#pragma unroll
    for (int ee = 0; ee < 16; ee++) {
        int el = e0 + ee;
        int s = snd[el];
        int r = rcv[el];
        float m0  = g_x0[s * 128 + f];
        float m1x = g_x1[(s * 128 + f) * 3 + 0];
        float m1y = g_x1[(s * 128 + f) * 3 + 1];
        float m1z = g_x1[(s * 128 + f) * 3 + 2];
        float Yx = y1s[el * 3 + 0], Yy = y1s[el * 3 + 1], Yz = y1s[el * 3 + 2];

        float mix0 = acc[0 * 16 + ee] * 0.125f;
        float mix1 = acc[1 * 16 + ee] * 0.125f;
        float mix2 = acc[2 * 16 + ee] * 0.125f;
        float mix3 = acc[3 * 16 + ee] * 0.125f;
        float mix4 = acc[4 * 16 + ee] * 0.125f;

        float dotf = (m1x * Yx + m1y * Yy + m1z * Yz) * INV_SQ3;
        float out0 = mix0 * m0 + mix1 * dotf;

        float ox = m0 * Yx * INV_SQ3;
        float oy = m0 * Yy * INV_SQ3;
        float oz = m0 * Yz * INV_SQ3;

        float cx = (m1y * Yz - m1z * Yy) * INV_SQ3;
        float cy = (m1z * Yx - m1x * Yz) * INV_SQ3;
        float cz = (m1x * Yy - m1y * Yx) * INV_SQ3;

        float o1x = mix2 * ox + mix3 * m1x + mix4 * cx;
        float o1y = mix2 * oy + mix3 * m1y + mix4 * cy;
        float o1z = mix2 * oz + mix3 * m1z + mix4 * cz;

        atomicAdd(&g_a0[r * 128 + f],           EPSf * out0);
        atomicAdd(&g_a1[(r * 128 + f) * 3 + 0], EPSf * o1x);
        atomicAdd(&g_a1[(r * 128 + f) * 3 + 1], EPSf * o1y);
        atomicAdd(&g_a1[(r * 128 + f) * 3 + 2], EPSf * o1z);
    }
}

// ---------------- node kernel: down + symcontract + post + skip + readout -----
// 8 nodes/block in species-bucket order (skip matrices stay L1-resident).
// 128 threads, thread = channel.
__global__ void __launch_bounds__(128) node_kernel(
    const float* __restrict__ nf0, const float* __restrict__ nf1,
    const int* __restrict__ species,
    const float* __restrict__ wz0, const float* __restrict__ wz1,
    const float* __restrict__ wd0, const float* __restrict__ wd1,
    const float* __restrict__ wsc,
    const float* __restrict__ wp0, const float* __restrict__ wp1,
    const float* __restrict__ wr0,
    float* __restrict__ out, int write_feats)
{
    __shared__ float sa0[8 * 128];
    __shared__ float sa1[8 * 384];
    __shared__ float sn0[8 * 128];
    __shared__ float sn1[8 * 384];
    __shared__ int   snid[8];
    __shared__ int   ssp[8];
    __shared__ float sred[8 * 4];

    const int t = threadIdx.x;
    const int bb = blockIdx.x * 8;

    if (t < 8) {
        int n = g_bucket[bb + t];
        snid[t] = n;
        ssp[t] = species[n];
    }
    __syncthreads();

#pragma unroll
    for (int jj = 0; jj < 8; jj++) {
        int n = snid[jj];
        sa0[jj * 128 + t] = g_a0[n * 128 + t];
        sn0[jj * 128 + t] = nf0[n * 128 + t];
        for (int idx = t; idx < 384; idx += 128) {
            sa1[jj * 384 + idx] = g_a1[n * 384 + idx];
            sn1[jj * 384 + idx] = nf1[n * 384 + idx];
        }
    }
    __syncthreads();

    float s[8], vx[8], vy[8], vz[8];
    float c0[8], cx[8], cy[8], cz[8];
#pragma unroll
    for (int jj = 0; jj < 8; jj++) {
        s[jj] = vx[jj] = vy[jj] = vz[jj] = 0.f;
        c0[jj] = cx[jj] = cy[jj] = cz[jj] = 0.f;
    }

    const float* pz0[8];
    const float* pz1[8];
#pragma unroll
    for (int jj = 0; jj < 8; jj++) {
        pz0[jj] = wz0 + ssp[jj] * (128 * 128);
        pz1[jj] = wz1 + ssp[jj] * (128 * 128);
    }

#pragma unroll 2
    for (int f = 0; f < 128; f++) {
        float w0v = wd0[f * 128 + t];
        float w1v = wd1[f * 128 + t];
#pragma unroll
        for (int jj = 0; jj < 8; jj++) {
            s[jj]  = fmaf(sa0[jj * 128 + f],         w0v, s[jj]);
            vx[jj] = fmaf(sa1[jj * 384 + f * 3 + 0], w1v, vx[jj]);
            vy[jj] = fmaf(sa1[jj * 384 + f * 3 + 1], w1v, vy[jj]);
            vz[jj] = fmaf(sa1[jj * 384 + f * 3 + 2], w1v, vz[jj]);
            float z0 = pz0[jj][f * 128 + t];
            float z1 = pz1[jj][f * 128 + t];
            c0[jj] = fmaf(sn0[jj * 128 + f],         z0, c0[jj]);
            cx[jj] = fmaf(sn1[jj * 384 + f * 3 + 0], z1, cx[jj]);
            cy[jj] = fmaf(sn1[jj * 384 + f * 3 + 1], z1, cy[jj]);
            cz[jj] = fmaf(sn1[jj * 384 + f * 3 + 2], z1, cz[jj]);
        }
    }
    __syncthreads();   // done reading sa*, will overwrite with b0/b1

    // symmetric contraction (fully elementwise in the channel index t)
#pragma unroll
    for (int jj = 0; jj < 8; jj++) {
        float sv  = s[jj] * INV_SQF;
        float vxx = vx[jj] * INV_SQF;
        float vyy = vy[jj] * INV_SQF;
        float vzz = vz[jj] * INV_SQF;
        float vv  = vxx * vxx + vyy * vyy + vzz * vzz;
        const float* w = wsc + ssp[jj] * (9 * 128);
        float w0 = w[0 * 128 + t] * INV_SQZ;
        float w1 = w[1 * 128 + t] * INV_SQZ;
        float w2 = w[2 * 128 + t] * INV_SQZ;
        float w3 = w[3 * 128 + t] * INV_SQZ;
        float w4 = w[4 * 128 + t] * INV_SQZ;
        float w5 = w[5 * 128 + t] * INV_SQZ;
        float w6 = w[6 * 128 + t] * INV_SQZ;
        float w7 = w[7 * 128 + t] * INV_SQZ;
        float w8 = w[8 * 128 + t] * INV_SQZ;
        float b0v = w0 * sv + w1 * sv * sv + w2 * vv + w3 * sv * sv * sv + w4 * sv * vv;
        float g1  = w5 + w6 * sv + w7 * sv * sv + w8 * vv;
        sa0[jj * 128 + t]         = b0v;
        sa1[jj * 384 + t * 3 + 0] = g1 * vxx;
        sa1[jj * 384 + t * 3 + 1] = g1 * vyy;
        sa1[jj * 384 + t * 3 + 2] = g1 * vzz;
    }
    __syncthreads();

    // post linear
    float f0[8], f1x[8], f1y[8], f1z[8];
#pragma unroll
    for (int jj = 0; jj < 8; jj++) { f0[jj] = f1x[jj] = f1y[jj] = f1z[jj] = 0.f; }

#pragma unroll 2
    for (int f = 0; f < 128; f++) {
        float w0v = wp0[f * 128 + t];
        float w1v = wp1[f * 128 + t];
#pragma unroll
        for (int jj = 0; jj < 8; jj++) {
            f0[jj]  = fmaf(sa0[jj * 128 + f],         w0v, f0[jj]);
            f1x[jj] = fmaf(sa1[jj * 384 + f * 3 + 0], w1v, f1x[jj]);
            f1y[jj] = fmaf(sa1[jj * 384 + f * 3 + 1], w1v, f1y[jj]);
            f1z[jj] = fmaf(sa1[jj * 384 + f * 3 + 2], w1v, f1z[jj]);
        }
    }

    float wrv = wr0[t];
#pragma unroll
    for (int jj = 0; jj < 8; jj++) {
        int n = snid[jj];
        float F0  = f0[jj]  * INV_SQF + c0[jj] * INV_SQFZ;
        float F1x = f1x[jj] * INV_SQF + cx[jj] * INV_SQFZ;
        float F1y = f1y[jj] * INV_SQF + cy[jj] * INV_SQFZ;
        float F1z = f1z[jj] * INV_SQF + cz[jj] * INV_SQFZ;

        if (write_feats) {
            out[NN + n * 128 + t]                      = F0;
            out[NN + NN * 128 + (n * 128 + t) * 3 + 0] = F1x;
            out[NN + NN * 128 + (n * 128 + t) * 3 + 1] = F1y;
            out[NN + NN * 128 + (n * 128 + t) * 3 + 2] = F1z;
        }

        float contrib = F0 * wrv;
#pragma unroll
        for (int off = 16; off > 0; off >>= 1)
            contrib += __shfl_xor_sync(0xffffffffu, contrib, off);
        if ((t & 31) == 0) sred[jj * 4 + (t >> 5)] = contrib;
    }
    __syncthreads();
    if (t < 8) {
        float r = (sred[t * 4 + 0] + sred[t * 4 + 1] + sred[t * 4 + 2] + sred[t * 4 + 3]) * INV_SQF;
        out[snid[t]] = r;
    }
}

// ---------------- launch ------------------------------------------------------
extern "C" void kernel_launch(void* const* d_in, const int* in_sizes, int n_in,
                              void* d_out, int out_size)
{
    const float* vectors   = (const float*)d_in[0];
    const float* nf0       = (const float*)d_in[1];
    const float* nf1       = (const float*)d_in[2];
    const float* radial    = (const float*)d_in[3];
    const int*   species   = (const int*)d_in[4];
    const int*   senders   = (const int*)d_in[5];
    const int*   receivers = (const int*)d_in[6];
    const float* wz0       = (const float*)d_in[7];
    const float* wz1       = (const float*)d_in[8];
    const float* wu0       = (const float*)d_in[9];
    const float* wu1       = (const float*)d_in[10];
    const float* mw1       = (const float*)d_in[11];
    const float* mw2       = (const float*)d_in[12];
    const float* mw3       = (const float*)d_in[13];
    const float* mw4       = (const float*)d_in[14];
    const float* wd0       = (const float*)d_in[15];
    const float* wd1       = (const float*)d_in[16];
    const float* wsc       = (const float*)d_in[17];
    const float* wp0       = (const float*)d_in[18];
    const float* wp1       = (const float*)d_in[19];
    const float* wr0       = (const float*)d_in[20];
    float* out = (float*)d_out;

    int write_feats = (out_size >= NN * (1 + 4 * FF)) ? 1 : 0;

    zero_kernel<<<1024, 256>>>();
    count_kernel<<<(NN + 255) / 256, 256>>>(species);
    scan_kernel<<<1, 32>>>();
    fill_kernel<<<(NN + 255) / 256, 256>>>(species);
    up_kernel<<<NN / 8, 128>>>(nf0, nf1, wu0, wu1);
    edge_kernel<<<NE / 32, 256>>>(vectors, radial, senders, receivers,
                                  mw1, mw2, mw3, mw4);
    node_kernel<<<NN / 8, 128>>>(nf0, nf1, species, wz0, wz1, wd0, wd1,
                                 wsc, wp0, wp1, wr0, out, write_feats);
}